// round 11
// baseline (speedup 1.0000x reference)
#include <cuda_runtime.h>
#include <cuda_fp16.h>
#include <math.h>
#include <stdint.h>

// Problem constants
#define NROWS   100352          // B*H*W = 32*56*56
#define CDIM    192
#define HID     768
#define QKVDIM  576
#define NHEAD   6
#define HDIM    32
#define NTOK    49
#define NWIN    64

// -------- scratch (device globals) --------
__device__ __half g_xw  [(size_t)NROWS * CDIM];     // LN outputs (f16)
__device__ __half g_qkv [(size_t)NROWS * QKVDIM];   // qkv (f16)
__device__ __half g_ao  [(size_t)NROWS * CDIM];     // attention out (f16)
__device__ float  g_x1  [(size_t)NROWS * CDIM];     // residual 1 (fp32)
__device__ __half g_h   [(size_t)NROWS * HID];      // MLP hidden (f16)
// transposed weights [N][K] K-major, f16
__device__ __half g_wt_qkv [QKVDIM * CDIM];
__device__ __half g_wt_proj[CDIM * CDIM];
__device__ __half g_wt_fc1 [HID * CDIM];
__device__ __half g_wt_fc2 [CDIM * HID];
// precomputed attention bias: [cls 0..3][head 0..5][i][j]
__device__ float  g_bias[4 * NHEAD * NTOK * NTOK];

// ================================================================
// PTX helpers
// ================================================================
__device__ __forceinline__ void cp16(uint32_t dst, const void* src) {
    asm volatile("cp.async.cg.shared.global [%0], [%1], 16;" :: "r"(dst), "l"(src));
}
__device__ __forceinline__ void cp_commit() {
    asm volatile("cp.async.commit_group;");
}
__device__ __forceinline__ void cp_wait0() {
    asm volatile("cp.async.wait_group 0;" ::: "memory");
}
__device__ __forceinline__ void ldm_x4(uint32_t r[4], uint32_t addr) {
    asm volatile("ldmatrix.sync.aligned.m8n8.x4.shared.b16 {%0,%1,%2,%3}, [%4];"
                 : "=r"(r[0]), "=r"(r[1]), "=r"(r[2]), "=r"(r[3]) : "r"(addr));
}
__device__ __forceinline__ void mma_f16(float d[4], const uint32_t a[4], const uint32_t b[2]) {
    asm volatile(
        "mma.sync.aligned.m16n8k16.row.col.f32.f16.f16.f32 "
        "{%0,%1,%2,%3}, {%4,%5,%6,%7}, {%8,%9}, {%0,%1,%2,%3};\n"
        : "+f"(d[0]), "+f"(d[1]), "+f"(d[2]), "+f"(d[3])
        : "r"(a[0]), "r"(a[1]), "r"(a[2]), "r"(a[3]), "r"(b[0]), "r"(b[1]));
}

// ================================================================
// Weight transpose + f16 convert: out[n*K + k] = (half)in[k*N + n]
// ================================================================
__global__ void transpose_kernel(const float* __restrict__ in, __half* __restrict__ out,
                                 int K, int N)
{
    int idx = blockIdx.x * 256 + threadIdx.x;
    if (idx >= K * N) return;
    int k = idx / N, n = idx % N;
    out[(size_t)n * K + k] = __float2half(in[idx]);
}

// ================================================================
// Attention bias precompute: bias[cls][head][i][j]
// cls bit1 = (wh==7), bit0 = (ww==7)
// ================================================================
__global__ void bias_kernel(const float* __restrict__ rpb_table,
                            float* __restrict__ bias)
{
    int cls  = blockIdx.y;            // 0..3
    int head = blockIdx.x;            // 0..5
    int wh7  = (cls >> 1) & 1;
    int ww7  = cls & 1;
    for (int idx = threadIdx.x; idx < NTOK * NTOK; idx += 256) {
        int i = idx / NTOK, j = idx % NTOK;
        int ih = i / 7, iw = i % 7, jh = j / 7, jw = j % 7;
        float b = rpb_table[((ih - jh + 6) * 13 + (iw - jw + 6)) * NHEAD + head];
        int hi = wh7 * 49 + ih, wi = ww7 * 49 + iw;
        int hj = wh7 * 49 + jh, wj = ww7 * 49 + jw;
        int ri = (hi < 49 ? 0 : (hi < 53 ? 1 : 2)) * 3 + (wi < 49 ? 0 : (wi < 53 ? 1 : 2));
        int rj = (hj < 49 ? 0 : (hj < 53 ? 1 : 2)) * 3 + (wj < 49 ? 0 : (wj < 53 ? 1 : 2));
        if (ri != rj) b -= 100.f;
        bias[((cls * NHEAD + head) * NTOK * NTOK) + idx] = b;
    }
}

// ================================================================
// F16 tensor-core GEMM (fp32 accumulate), ldmatrix, 2-stage cp.async.
// BM=128, BN=64, BK=32(half), 128 threads (4 warps), warp tile 64x32.
// EPI: 0 none->half, 1 GELU->half, 2 residual->float, 3 scatter residual->float
// ================================================================
#define AS_STR  40                  // halves (80 B rows)
#define A_H     (128 * AS_STR)      // 5120 halves
#define B_H     (64 * AS_STR)       // 2560 halves
#define STAGE_H (A_H + B_H)         // 7680 halves (15360 B)
#define STAGES  2

template <int EPI>
__global__ void __launch_bounds__(128)
mma_gemm(const __half* __restrict__ A,
         const __half* __restrict__ WT,
         const float* __restrict__ bias,
         void* __restrict__ Cv,
         const float* __restrict__ res,
         int M, int N, int K)
{
    __shared__ __align__(16) __half sm[STAGES * STAGE_H];

    const int t    = threadIdx.x;
    const int bm   = blockIdx.y * 128;
    const int bn   = blockIdx.x * 64;
    const int lane = t & 31;
    const int w    = t >> 5;
    const int g    = lane >> 2;
    const int tig  = lane & 3;
    const int q    = lane >> 3;
    const int r8   = lane & 7;
    const int wm   = (w & 1) * 64;
    const int wn   = (w >> 1) * 32;

    float acc[4][4][4] = {};

    auto issue = [&](int stage, int kt) {
        __half* As = sm + stage * STAGE_H;
        __half* Bs = As + A_H;
        #pragma unroll
        for (int i = 0; i < 4; i++) {
            int f   = t + i * 128;
            int row = f >> 2;
            int c8  = (f & 3) * 8;
            cp16((uint32_t)__cvta_generic_to_shared(As + row * AS_STR + c8),
                 A + (size_t)(bm + row) * K + kt * 32 + c8);
        }
        #pragma unroll
        for (int i = 0; i < 2; i++) {
            int f   = t + i * 128;
            int row = f >> 2;
            int c8  = (f & 3) * 8;
            cp16((uint32_t)__cvta_generic_to_shared(Bs + row * AS_STR + c8),
                 WT + (size_t)(bn + row) * K + kt * 32 + c8);
        }
    };

    auto compute = [&](int stage) {
        const __half* As = sm + stage * STAGE_H;
        const __half* Bs = As + A_H;
        #pragma unroll
        for (int ks = 0; ks < 32; ks += 16) {
            uint32_t a[4][4];
            uint32_t b[4][2];
            #pragma unroll
            for (int mb = 0; mb < 4; mb++) {
                uint32_t addr = (uint32_t)__cvta_generic_to_shared(
                    As + (wm + mb * 16 + (q & 1) * 8 + r8) * AS_STR + ks + (q >> 1) * 8);
                ldm_x4(a[mb], addr);
            }
            #pragma unroll
            for (int nb2 = 0; nb2 < 2; nb2++) {
                uint32_t bt[4];
                uint32_t addr = (uint32_t)__cvta_generic_to_shared(
                    Bs + (wn + nb2 * 16 + (q >> 1) * 8 + r8) * AS_STR + ks + (q & 1) * 8);
                ldm_x4(bt, addr);
                b[nb2 * 2 + 0][0] = bt[0]; b[nb2 * 2 + 0][1] = bt[1];
                b[nb2 * 2 + 1][0] = bt[2]; b[nb2 * 2 + 1][1] = bt[3];
            }
            #pragma unroll
            for (int mi = 0; mi < 4; mi++)
                #pragma unroll
                for (int ni = 0; ni < 4; ni++)
                    mma_f16(acc[mi][ni], a[mi], b[ni]);
        }
    };

    const int KT = K >> 5;
    issue(0, 0); cp_commit();

    for (int kt = 0; kt < KT; kt++) {
        cp_wait0();                      // tile kt landed
        __syncthreads();                 // everyone done computing kt-1
        if (kt + 1 < KT) { issue((kt + 1) & 1, kt + 1); cp_commit(); }
        compute(kt & 1);
    }

    // ---- epilogue ----
    float2 bia[4];
    #pragma unroll
    for (int ni = 0; ni < 4; ni++)
        bia[ni] = *(const float2*)(bias + bn + wn + ni * 8 + tig * 2);

    #pragma unroll
    for (int mi = 0; mi < 4; mi++) {
        #pragma unroll
        for (int half_ = 0; half_ < 2; half_++) {
            int row = bm + wm + mi * 16 + g + half_ * 8;
            size_t rowoff;
            if (EPI == 3) {
                int bb  = row / 3136;
                int rem = row % 3136;
                int win = rem / NTOK;
                int n   = rem % NTOK;
                int h_s = (win >> 3) * 7 + n / 7;
                int w_s = (win & 7) * 7 + n % 7;
                int hh = (h_s + 3) % 56;
                int ww = (w_s + 3) % 56;
                rowoff = ((size_t)bb * 3136 + hh * 56 + ww) * CDIM;
            } else {
                rowoff = (size_t)row * N;
            }
            #pragma unroll
            for (int ni = 0; ni < 4; ni++) {
                int col = bn + wn + ni * 8 + tig * 2;
                float v0 = acc[mi][ni][half_ * 2 + 0] + bia[ni].x;
                float v1 = acc[mi][ni][half_ * 2 + 1] + bia[ni].y;
                size_t o = rowoff + col;
                if (EPI == 0) {
                    *(__half2*)((__half*)Cv + o) = __floats2half2_rn(v0, v1);
                } else if (EPI == 1) {
                    v0 = 0.5f * v0 * (1.f + erff(v0 * 0.70710678118654752f));
                    v1 = 0.5f * v1 * (1.f + erff(v1 * 0.70710678118654752f));
                    *(__half2*)((__half*)Cv + o) = __floats2half2_rn(v0, v1);
                } else {
                    float2 rr = *(const float2*)(res + o);
                    v0 += rr.x; v1 += rr.y;
                    *(float2*)((float*)Cv + o) = make_float2(v0, v1);
                }
            }
        }
    }
}

// ================================================================
// LayerNorm (mode 1: shift+window gather for ln1; mode 0: identity)
// fp32 in -> f16 out
// ================================================================
__global__ void ln_kernel(const float* __restrict__ x,
                          const float* __restrict__ gw,
                          const float* __restrict__ gb,
                          __half* __restrict__ out, int mode)
{
    int warp = (blockIdx.x * blockDim.x + threadIdx.x) >> 5;
    int lane = threadIdx.x & 31;
    if (warp >= NROWS) return;

    const float* src;
    if (mode == 1) {
        int bb  = warp / 3136;
        int rem = warp % 3136;
        int win = rem / NTOK;
        int n   = rem % NTOK;
        int h_s = (win >> 3) * 7 + n / 7;
        int w_s = (win & 7) * 7 + n % 7;
        int hh = (h_s + 3) % 56;
        int ww = (w_s + 3) % 56;
        src = x + ((size_t)bb * 3136 + hh * 56 + ww) * CDIM;
    } else {
        src = x + (size_t)warp * CDIM;
    }

    float v[6];
    float s = 0.f, sq = 0.f;
    #pragma unroll
    for (int k = 0; k < 6; k++) {
        v[k] = src[lane + 32 * k];
        s += v[k];
        sq += v[k] * v[k];
    }
    #pragma unroll
    for (int o = 16; o; o >>= 1) {
        s  += __shfl_xor_sync(0xFFFFFFFFu, s, o);
        sq += __shfl_xor_sync(0xFFFFFFFFu, sq, o);
    }
    float mu  = s * (1.f / 192.f);
    float var = sq * (1.f / 192.f) - mu * mu;
    float rs  = rsqrtf(var + 1e-5f);

    __half* dst = out + (size_t)warp * CDIM;
    #pragma unroll
    for (int k = 0; k < 6; k++) {
        int c = lane + 32 * k;
        dst[c] = __float2half((v[k] - mu) * rs * gw[c] + gb[c]);
    }
}

// ================================================================
// Windowed attention; f16 qkv in, f16 ao out, precomputed bias
// ================================================================
#define QSTR 36
__global__ void __launch_bounds__(256)
attn_kernel(const __half* __restrict__ qkv,
            const float* __restrict__ biastab,
            __half* __restrict__ ao)
{
    __shared__ __align__(16) float qs[NTOK * QSTR];
    __shared__ __align__(16) float ks[NTOK * QSTR];
    __shared__ __align__(16) float vs[NTOK * QSTR];
    __shared__ float sc[NTOK][NTOK + 1];

    const int bid  = blockIdx.x;
    const int head = bid % NHEAD;
    const int win  = (bid / NHEAD) % NWIN;
    const int bb   = bid / (NHEAD * NWIN);
    const int tid  = threadIdx.x;

    const size_t baserow = (size_t)(bb * NWIN + win) * NTOK;
    const int wh = win >> 3, ww = win & 7;
    const int cls = ((wh == 7) ? 2 : 0) | ((ww == 7) ? 1 : 0);
    const float* bp = biastab + (cls * NHEAD + head) * (NTOK * NTOK);

    for (int idx = tid; idx < NTOK * 8; idx += 256) {
        int n = idx >> 3, d4 = idx & 7;
        const __half2* p = (const __half2*)(qkv + (baserow + n) * QKVDIM + head * HDIM + d4 * 4);
        float2 a0 = __half22float2(p[0]);
        float2 a1 = __half22float2(p[1]);
        *(float4*)(qs + n * QSTR + d4 * 4) = make_float4(a0.x, a0.y, a1.x, a1.y);
        const __half2* pk = p + CDIM / 2;
        float2 b0 = __half22float2(pk[0]);
        float2 b1 = __half22float2(pk[1]);
        *(float4*)(ks + n * QSTR + d4 * 4) = make_float4(b0.x, b0.y, b1.x, b1.y);
        const __half2* pv = p + CDIM;
        float2 c0 = __half22float2(pv[0]);
        float2 c1 = __half22float2(pv[1]);
        *(float4*)(vs + n * QSTR + d4 * 4) = make_float4(c0.x, c0.y, c1.x, c1.y);
    }
    __syncthreads();

    const float scale = 0.17677669529663687f;

    for (int idx = tid; idx < NTOK * NTOK; idx += 256) {
        int i = idx / NTOK, j = idx % NTOK;
        const float4* q4 = (const float4*)(qs + i * QSTR);
        const float4* k4 = (const float4*)(ks + j * QSTR);
        float s = 0.f;
        #pragma unroll
        for (int d = 0; d < 8; d++) {
            float4 a = q4[d], b = k4[d];
            s += a.x * b.x + a.y * b.y + a.z * b.z + a.w * b.w;
        }
        sc[i][j] = s * scale + bp[idx];
    }
    __syncthreads();

    int warp = tid >> 5, lane = tid & 31;
    for (int i = warp; i < NTOK; i += 8) {
        float m = -1e30f;
        for (int j = lane; j < NTOK; j += 32) m = fmaxf(m, sc[i][j]);
        #pragma unroll
        for (int o = 16; o; o >>= 1) m = fmaxf(m, __shfl_xor_sync(0xFFFFFFFFu, m, o));
        float sum = 0.f;
        for (int j = lane; j < NTOK; j += 32) {
            float e = expf(sc[i][j] - m);
            sc[i][j] = e;
            sum += e;
        }
        #pragma unroll
        for (int o = 16; o; o >>= 1) sum += __shfl_xor_sync(0xFFFFFFFFu, sum, o);
        float inv = 1.f / sum;
        for (int j = lane; j < NTOK; j += 32) sc[i][j] *= inv;
    }
    __syncthreads();

    for (int idx = tid; idx < NTOK * 8; idx += 256) {
        int i = idx >> 3, d4 = idx & 7;
        float4 o = make_float4(0.f, 0.f, 0.f, 0.f);
        const float* sci = sc[i];
        #pragma unroll 7
        for (int j = 0; j < NTOK; j++) {
            float wv = sci[j];
            float4 v = *(const float4*)(vs + j * QSTR + d4 * 4);
            o.x += wv * v.x; o.y += wv * v.y; o.z += wv * v.z; o.w += wv * v.w;
        }
        __half2* dst = (__half2*)(ao + (baserow + i) * CDIM + head * HDIM + d4 * 4);
        dst[0] = __floats2half2_rn(o.x, o.y);
        dst[1] = __floats2half2_rn(o.z, o.w);
    }
}

// ================================================================
extern "C" void kernel_launch(void* const* d_in, const int* in_sizes, int n_in,
                              void* d_out, int out_size)
{
    const float* x       = (const float*)d_in[0];
    const float* norm1_g = (const float*)d_in[1];
    const float* norm1_b = (const float*)d_in[2];
    const float* qkv_w   = (const float*)d_in[3];
    const float* qkv_b   = (const float*)d_in[4];
    const float* rpb_t   = (const float*)d_in[5];
    const float* proj_w  = (const float*)d_in[6];
    const float* proj_b  = (const float*)d_in[7];
    const float* norm2_g = (const float*)d_in[8];
    const float* norm2_b = (const float*)d_in[9];
    const float* fc1_w   = (const float*)d_in[10];
    const float* fc1_b   = (const float*)d_in[11];
    const float* fc2_w   = (const float*)d_in[12];
    const float* fc2_b   = (const float*)d_in[13];
    float* out = (float*)d_out;

    __half *xw, *qkvbuf, *ao, *hbuf, *wt_qkv, *wt_proj, *wt_fc1, *wt_fc2;
    float *x1, *biastab;
    cudaGetSymbolAddress((void**)&xw,      g_xw);
    cudaGetSymbolAddress((void**)&qkvbuf,  g_qkv);
    cudaGetSymbolAddress((void**)&ao,      g_ao);
    cudaGetSymbolAddress((void**)&x1,      g_x1);
    cudaGetSymbolAddress((void**)&hbuf,    g_h);
    cudaGetSymbolAddress((void**)&wt_qkv,  g_wt_qkv);
    cudaGetSymbolAddress((void**)&wt_proj, g_wt_proj);
    cudaGetSymbolAddress((void**)&wt_fc1,  g_wt_fc1);
    cudaGetSymbolAddress((void**)&wt_fc2,  g_wt_fc2);
    cudaGetSymbolAddress((void**)&biastab, g_bias);

    const int lnGrid = (NROWS + 7) / 8;

    // 0. Weight transposes + bias table
    transpose_kernel<<<(CDIM * QKVDIM + 255) / 256, 256>>>(qkv_w,  wt_qkv,  CDIM, QKVDIM);
    transpose_kernel<<<(CDIM * CDIM   + 255) / 256, 256>>>(proj_w, wt_proj, CDIM, CDIM);
    transpose_kernel<<<(CDIM * HID    + 255) / 256, 256>>>(fc1_w,  wt_fc1,  CDIM, HID);
    transpose_kernel<<<(HID  * CDIM   + 255) / 256, 256>>>(fc2_w,  wt_fc2,  HID,  CDIM);
    bias_kernel<<<dim3(NHEAD, 4), 256>>>(rpb_t, biastab);

    // 1. LN1 + shift + window partition (f16 out)
    ln_kernel<<<lnGrid, 256>>>(x, norm1_g, norm1_b, xw, 1);

    // 2. QKV GEMM [100352,192] @ [192,576] -> f16 qkv
    mma_gemm<0><<<dim3(QKVDIM / 64, NROWS / 128), 128>>>(
        xw, wt_qkv, qkv_b, qkvbuf, nullptr, NROWS, QKVDIM, CDIM);

    // 3. Windowed attention -> f16 ao
    attn_kernel<<<32 * NWIN * NHEAD, 256>>>(qkvbuf, biastab, ao);

    // 4. Projection GEMM + fused un-shift/un-window + residual -> fp32 x1
    mma_gemm<3><<<dim3(CDIM / 64, NROWS / 128), 128>>>(
        ao, wt_proj, proj_b, x1, x, NROWS, CDIM, CDIM);

    // 5. LN2 (f16 out)
    ln_kernel<<<lnGrid, 256>>>(x1, norm2_g, norm2_b, xw, 0);

    // 6. FC1 + exact GELU [100352,192] @ [192,768] -> f16 hidden
    mma_gemm<1><<<dim3(HID / 64, NROWS / 128), 128>>>(
        xw, wt_fc1, fc1_b, hbuf, nullptr, NROWS, HID, CDIM);

    // 7. FC2 + residual [100352,768] @ [768,192] -> fp32 d_out
    mma_gemm<2><<<dim3(CDIM / 64, NROWS / 128), 128>>>(
        hbuf, wt_fc2, fc2_b, out, x1, NROWS, CDIM, HID);
}

// round 12
// speedup vs baseline: 1.0172x; 1.0172x over previous
#include <cuda_runtime.h>
#include <cuda_fp16.h>
#include <math.h>
#include <stdint.h>

// Problem constants
#define NROWS   100352          // B*H*W = 32*56*56
#define CDIM    192
#define HID     768
#define QKVDIM  576
#define NHEAD   6
#define HDIM    32
#define NTOK    49
#define NWIN    64

// -------- scratch (device globals) --------
__device__ __half g_xw  [(size_t)NROWS * CDIM];     // LN outputs (f16)
__device__ __half g_qkv [(size_t)NROWS * QKVDIM];   // qkv (f16)
__device__ __half g_ao  [(size_t)NROWS * CDIM];     // attention out (f16)
__device__ float  g_x1  [(size_t)NROWS * CDIM];     // residual 1 (fp32)
__device__ __half g_h   [(size_t)NROWS * HID];      // MLP hidden (f16)
// transposed weights [N][K] K-major, f16
__device__ __half g_wt_qkv [QKVDIM * CDIM];
__device__ __half g_wt_proj[CDIM * CDIM];
__device__ __half g_wt_fc1 [HID * CDIM];
__device__ __half g_wt_fc2 [CDIM * HID];
// precomputed attention bias: [cls 0..3][head 0..5][i][j]
__device__ float  g_bias[4 * NHEAD * NTOK * NTOK];

// ================================================================
// PTX helpers
// ================================================================
__device__ __forceinline__ void cp16(uint32_t dst, const void* src) {
    asm volatile("cp.async.cg.shared.global [%0], [%1], 16;" :: "r"(dst), "l"(src));
}
__device__ __forceinline__ void cp_commit() {
    asm volatile("cp.async.commit_group;");
}
__device__ __forceinline__ void cp_wait1() {
    asm volatile("cp.async.wait_group 1;" ::: "memory");
}
__device__ __forceinline__ void ldm_x4(uint32_t r[4], uint32_t addr) {
    asm volatile("ldmatrix.sync.aligned.m8n8.x4.shared.b16 {%0,%1,%2,%3}, [%4];"
                 : "=r"(r[0]), "=r"(r[1]), "=r"(r[2]), "=r"(r[3]) : "r"(addr));
}
__device__ __forceinline__ void mma_f16(float d[4], const uint32_t a[4], const uint32_t b[2]) {
    asm volatile(
        "mma.sync.aligned.m16n8k16.row.col.f32.f16.f16.f32 "
        "{%0,%1,%2,%3}, {%4,%5,%6,%7}, {%8,%9}, {%0,%1,%2,%3};\n"
        : "+f"(d[0]), "+f"(d[1]), "+f"(d[2]), "+f"(d[3])
        : "r"(a[0]), "r"(a[1]), "r"(a[2]), "r"(a[3]), "r"(b[0]), "r"(b[1]));
}

// ================================================================
// Weight transpose + f16 convert: out[n*K + k] = (half)in[k*N + n]
// ================================================================
__global__ void transpose_kernel(const float* __restrict__ in, __half* __restrict__ out,
                                 int K, int N)
{
    int idx = blockIdx.x * 256 + threadIdx.x;
    if (idx >= K * N) return;
    int k = idx / N, n = idx % N;
    out[(size_t)n * K + k] = __float2half(in[idx]);
}

// ================================================================
// Attention bias precompute: bias[cls][head][i][j]
// cls bit1 = (wh==7), bit0 = (ww==7)
// ================================================================
__global__ void bias_kernel(const float* __restrict__ rpb_table,
                            float* __restrict__ bias)
{
    int cls  = blockIdx.y;            // 0..3
    int head = blockIdx.x;            // 0..5
    int wh7  = (cls >> 1) & 1;
    int ww7  = cls & 1;
    for (int idx = threadIdx.x; idx < NTOK * NTOK; idx += 256) {
        int i = idx / NTOK, j = idx % NTOK;
        int ih = i / 7, iw = i % 7, jh = j / 7, jw = j % 7;
        float b = rpb_table[((ih - jh + 6) * 13 + (iw - jw + 6)) * NHEAD + head];
        int hi = wh7 * 49 + ih, wi = ww7 * 49 + iw;
        int hj = wh7 * 49 + jh, wj = ww7 * 49 + jw;
        int ri = (hi < 49 ? 0 : (hi < 53 ? 1 : 2)) * 3 + (wi < 49 ? 0 : (wi < 53 ? 1 : 2));
        int rj = (hj < 49 ? 0 : (hj < 53 ? 1 : 2)) * 3 + (wj < 49 ? 0 : (wj < 53 ? 1 : 2));
        if (ri != rj) b -= 100.f;
        bias[((cls * NHEAD + head) * NTOK * NTOK) + idx] = b;
    }
}

// ================================================================
// F16 tensor-core GEMM (fp32 accumulate), ldmatrix, 3-stage cp.async.
// BM=128, BN=64, BK=32(half), 128 threads (4 warps), warp tile 64x32.
// EPI: 0 none->half, 1 GELU->half, 2 residual->float, 3 scatter residual->float
// ================================================================
#define AS_STR  40                  // halves (80 B rows)
#define A_H     (128 * AS_STR)      // 5120 halves
#define B_H     (64 * AS_STR)       // 2560 halves
#define STAGE_H (A_H + B_H)         // 7680 halves (15360 B)
#define STAGES  3

template <int EPI>
__global__ void __launch_bounds__(128)
mma_gemm(const __half* __restrict__ A,
         const __half* __restrict__ WT,
         const float* __restrict__ bias,
         void* __restrict__ Cv,
         const float* __restrict__ res,
         int M, int N, int K)
{
    __shared__ __align__(16) __half sm[STAGES * STAGE_H];

    const int t    = threadIdx.x;
    const int bm   = blockIdx.y * 128;
    const int bn   = blockIdx.x * 64;
    const int lane = t & 31;
    const int w    = t >> 5;
    const int g    = lane >> 2;
    const int tig  = lane & 3;
    const int q    = lane >> 3;
    const int r8   = lane & 7;
    const int wm   = (w & 1) * 64;
    const int wn   = (w >> 1) * 32;

    float acc[4][4][4] = {};

    auto issue = [&](int stage, int kt) {
        __half* As = sm + stage * STAGE_H;
        __half* Bs = As + A_H;
        #pragma unroll
        for (int i = 0; i < 4; i++) {
            int f   = t + i * 128;
            int row = f >> 2;
            int c8  = (f & 3) * 8;
            cp16((uint32_t)__cvta_generic_to_shared(As + row * AS_STR + c8),
                 A + (size_t)(bm + row) * K + kt * 32 + c8);
        }
        #pragma unroll
        for (int i = 0; i < 2; i++) {
            int f   = t + i * 128;
            int row = f >> 2;
            int c8  = (f & 3) * 8;
            cp16((uint32_t)__cvta_generic_to_shared(Bs + row * AS_STR + c8),
                 WT + (size_t)(bn + row) * K + kt * 32 + c8);
        }
    };

    auto compute = [&](int stage) {
        const __half* As = sm + stage * STAGE_H;
        const __half* Bs = As + A_H;
        #pragma unroll
        for (int ks = 0; ks < 32; ks += 16) {
            uint32_t a[4][4];
            uint32_t b[4][2];
            #pragma unroll
            for (int mb = 0; mb < 4; mb++) {
                uint32_t addr = (uint32_t)__cvta_generic_to_shared(
                    As + (wm + mb * 16 + (q & 1) * 8 + r8) * AS_STR + ks + (q >> 1) * 8);
                ldm_x4(a[mb], addr);
            }
            #pragma unroll
            for (int nb2 = 0; nb2 < 2; nb2++) {
                uint32_t bt[4];
                uint32_t addr = (uint32_t)__cvta_generic_to_shared(
                    Bs + (wn + nb2 * 16 + (q >> 1) * 8 + r8) * AS_STR + ks + (q & 1) * 8);
                ldm_x4(bt, addr);
                b[nb2 * 2 + 0][0] = bt[0]; b[nb2 * 2 + 0][1] = bt[1];
                b[nb2 * 2 + 1][0] = bt[2]; b[nb2 * 2 + 1][1] = bt[3];
            }
            #pragma unroll
            for (int mi = 0; mi < 4; mi++)
                #pragma unroll
                for (int ni = 0; ni < 4; ni++)
                    mma_f16(acc[mi][ni], a[mi], b[ni]);
        }
    };

    const int KT = K >> 5;
    issue(0, 0); cp_commit();
    issue(1, 1); cp_commit();

    for (int kt = 0; kt < KT; kt++) {
        cp_wait1();                      // tile kt landed (one group may be in flight)
        __syncthreads();                 // everyone done reading stage (kt+2)%3
        if (kt + 2 < KT) issue((kt + 2) % 3, kt + 2);
        cp_commit();
        compute(kt % 3);
    }

    // ---- epilogue ----
    float2 bia[4];
    #pragma unroll
    for (int ni = 0; ni < 4; ni++)
        bia[ni] = *(const float2*)(bias + bn + wn + ni * 8 + tig * 2);

    #pragma unroll
    for (int mi = 0; mi < 4; mi++) {
        #pragma unroll
        for (int half_ = 0; half_ < 2; half_++) {
            int row = bm + wm + mi * 16 + g + half_ * 8;
            size_t rowoff;
            if (EPI == 3) {
                int bb  = row / 3136;
                int rem = row % 3136;
                int win = rem / NTOK;
                int n   = rem % NTOK;
                int h_s = (win >> 3) * 7 + n / 7;
                int w_s = (win & 7) * 7 + n % 7;
                int hh = (h_s + 3) % 56;
                int ww = (w_s + 3) % 56;
                rowoff = ((size_t)bb * 3136 + hh * 56 + ww) * CDIM;
            } else {
                rowoff = (size_t)row * N;
            }
            #pragma unroll
            for (int ni = 0; ni < 4; ni++) {
                int col = bn + wn + ni * 8 + tig * 2;
                float v0 = acc[mi][ni][half_ * 2 + 0] + bia[ni].x;
                float v1 = acc[mi][ni][half_ * 2 + 1] + bia[ni].y;
                size_t o = rowoff + col;
                if (EPI == 0) {
                    *(__half2*)((__half*)Cv + o) = __floats2half2_rn(v0, v1);
                } else if (EPI == 1) {
                    v0 = 0.5f * v0 * (1.f + erff(v0 * 0.70710678118654752f));
                    v1 = 0.5f * v1 * (1.f + erff(v1 * 0.70710678118654752f));
                    *(__half2*)((__half*)Cv + o) = __floats2half2_rn(v0, v1);
                } else {
                    float2 rr = *(const float2*)(res + o);
                    v0 += rr.x; v1 += rr.y;
                    *(float2*)((float*)Cv + o) = make_float2(v0, v1);
                }
            }
        }
    }
}

// ================================================================
// LayerNorm (mode 1: shift+window gather for ln1; mode 0: identity)
// fp32 in -> f16 out
// ================================================================
__global__ void ln_kernel(const float* __restrict__ x,
                          const float* __restrict__ gw,
                          const float* __restrict__ gb,
                          __half* __restrict__ out, int mode)
{
    int warp = (blockIdx.x * blockDim.x + threadIdx.x) >> 5;
    int lane = threadIdx.x & 31;
    if (warp >= NROWS) return;

    const float* src;
    if (mode == 1) {
        int bb  = warp / 3136;
        int rem = warp % 3136;
        int win = rem / NTOK;
        int n   = rem % NTOK;
        int h_s = (win >> 3) * 7 + n / 7;
        int w_s = (win & 7) * 7 + n % 7;
        int hh = (h_s + 3) % 56;
        int ww = (w_s + 3) % 56;
        src = x + ((size_t)bb * 3136 + hh * 56 + ww) * CDIM;
    } else {
        src = x + (size_t)warp * CDIM;
    }

    float v[6];
    float s = 0.f, sq = 0.f;
    #pragma unroll
    for (int k = 0; k < 6; k++) {
        v[k] = src[lane + 32 * k];
        s += v[k];
        sq += v[k] * v[k];
    }
    #pragma unroll
    for (int o = 16; o; o >>= 1) {
        s  += __shfl_xor_sync(0xFFFFFFFFu, s, o);
        sq += __shfl_xor_sync(0xFFFFFFFFu, sq, o);
    }
    float mu  = s * (1.f / 192.f);
    float var = sq * (1.f / 192.f) - mu * mu;
    float rs  = rsqrtf(var + 1e-5f);

    __half* dst = out + (size_t)warp * CDIM;
    #pragma unroll
    for (int k = 0; k < 6; k++) {
        int c = lane + 32 * k;
        dst[c] = __float2half((v[k] - mu) * rs * gw[c] + gb[c]);
    }
}

// ================================================================
// Windowed attention; f16 qkv in, f16 ao out, precomputed bias
// ================================================================
#define QSTR 36
__global__ void __launch_bounds__(256)
attn_kernel(const __half* __restrict__ qkv,
            const float* __restrict__ biastab,
            __half* __restrict__ ao)
{
    __shared__ __align__(16) float qs[NTOK * QSTR];
    __shared__ __align__(16) float ks[NTOK * QSTR];
    __shared__ __align__(16) float vs[NTOK * QSTR];
    __shared__ float sc[NTOK][NTOK + 1];

    const int bid  = blockIdx.x;
    const int head = bid % NHEAD;
    const int win  = (bid / NHEAD) % NWIN;
    const int bb   = bid / (NHEAD * NWIN);
    const int tid  = threadIdx.x;

    const size_t baserow = (size_t)(bb * NWIN + win) * NTOK;
    const int wh = win >> 3, ww = win & 7;
    const int cls = ((wh == 7) ? 2 : 0) | ((ww == 7) ? 1 : 0);
    const float* bp = biastab + (cls * NHEAD + head) * (NTOK * NTOK);

    for (int idx = tid; idx < NTOK * 8; idx += 256) {
        int n = idx >> 3, d4 = idx & 7;
        const __half2* p = (const __half2*)(qkv + (baserow + n) * QKVDIM + head * HDIM + d4 * 4);
        float2 a0 = __half22float2(p[0]);
        float2 a1 = __half22float2(p[1]);
        *(float4*)(qs + n * QSTR + d4 * 4) = make_float4(a0.x, a0.y, a1.x, a1.y);
        const __half2* pk = p + CDIM / 2;
        float2 b0 = __half22float2(pk[0]);
        float2 b1 = __half22float2(pk[1]);
        *(float4*)(ks + n * QSTR + d4 * 4) = make_float4(b0.x, b0.y, b1.x, b1.y);
        const __half2* pv = p + CDIM;
        float2 c0 = __half22float2(pv[0]);
        float2 c1 = __half22float2(pv[1]);
        *(float4*)(vs + n * QSTR + d4 * 4) = make_float4(c0.x, c0.y, c1.x, c1.y);
    }
    __syncthreads();

    const float scale = 0.17677669529663687f;

    for (int idx = tid; idx < NTOK * NTOK; idx += 256) {
        int i = idx / NTOK, j = idx % NTOK;
        const float4* q4 = (const float4*)(qs + i * QSTR);
        const float4* k4 = (const float4*)(ks + j * QSTR);
        float s = 0.f;
        #pragma unroll
        for (int d = 0; d < 8; d++) {
            float4 a = q4[d], b = k4[d];
            s += a.x * b.x + a.y * b.y + a.z * b.z + a.w * b.w;
        }
        sc[i][j] = s * scale + bp[idx];
    }
    __syncthreads();

    int warp = tid >> 5, lane = tid & 31;
    for (int i = warp; i < NTOK; i += 8) {
        float m = -1e30f;
        for (int j = lane; j < NTOK; j += 32) m = fmaxf(m, sc[i][j]);
        #pragma unroll
        for (int o = 16; o; o >>= 1) m = fmaxf(m, __shfl_xor_sync(0xFFFFFFFFu, m, o));
        float sum = 0.f;
        for (int j = lane; j < NTOK; j += 32) {
            float e = expf(sc[i][j] - m);
            sc[i][j] = e;
            sum += e;
        }
        #pragma unroll
        for (int o = 16; o; o >>= 1) sum += __shfl_xor_sync(0xFFFFFFFFu, sum, o);
        float inv = 1.f / sum;
        for (int j = lane; j < NTOK; j += 32) sc[i][j] *= inv;
    }
    __syncthreads();

    for (int idx = tid; idx < NTOK * 8; idx += 256) {
        int i = idx >> 3, d4 = idx & 7;
        float4 o = make_float4(0.f, 0.f, 0.f, 0.f);
        const float* sci = sc[i];
        #pragma unroll 7
        for (int j = 0; j < NTOK; j++) {
            float wv = sci[j];
            float4 v = *(const float4*)(vs + j * QSTR + d4 * 4);
            o.x += wv * v.x; o.y += wv * v.y; o.z += wv * v.z; o.w += wv * v.w;
        }
        __half2* dst = (__half2*)(ao + (baserow + i) * CDIM + head * HDIM + d4 * 4);
        dst[0] = __floats2half2_rn(o.x, o.y);
        dst[1] = __floats2half2_rn(o.z, o.w);
    }
}

// ================================================================
extern "C" void kernel_launch(void* const* d_in, const int* in_sizes, int n_in,
                              void* d_out, int out_size)
{
    const float* x       = (const float*)d_in[0];
    const float* norm1_g = (const float*)d_in[1];
    const float* norm1_b = (const float*)d_in[2];
    const float* qkv_w   = (const float*)d_in[3];
    const float* qkv_b   = (const float*)d_in[4];
    const float* rpb_t   = (const float*)d_in[5];
    const float* proj_w  = (const float*)d_in[6];
    const float* proj_b  = (const float*)d_in[7];
    const float* norm2_g = (const float*)d_in[8];
    const float* norm2_b = (const float*)d_in[9];
    const float* fc1_w   = (const float*)d_in[10];
    const float* fc1_b   = (const float*)d_in[11];
    const float* fc2_w   = (const float*)d_in[12];
    const float* fc2_b   = (const float*)d_in[13];
    float* out = (float*)d_out;

    __half *xw, *qkvbuf, *ao, *hbuf, *wt_qkv, *wt_proj, *wt_fc1, *wt_fc2;
    float *x1, *biastab;
    cudaGetSymbolAddress((void**)&xw,      g_xw);
    cudaGetSymbolAddress((void**)&qkvbuf,  g_qkv);
    cudaGetSymbolAddress((void**)&ao,      g_ao);
    cudaGetSymbolAddress((void**)&x1,      g_x1);
    cudaGetSymbolAddress((void**)&hbuf,    g_h);
    cudaGetSymbolAddress((void**)&wt_qkv,  g_wt_qkv);
    cudaGetSymbolAddress((void**)&wt_proj, g_wt_proj);
    cudaGetSymbolAddress((void**)&wt_fc1,  g_wt_fc1);
    cudaGetSymbolAddress((void**)&wt_fc2,  g_wt_fc2);
    cudaGetSymbolAddress((void**)&biastab, g_bias);

    const int lnGrid = (NROWS + 7) / 8;

    // 0. Weight transposes + bias table
    transpose_kernel<<<(CDIM * QKVDIM + 255) / 256, 256>>>(qkv_w,  wt_qkv,  CDIM, QKVDIM);
    transpose_kernel<<<(CDIM * CDIM   + 255) / 256, 256>>>(proj_w, wt_proj, CDIM, CDIM);
    transpose_kernel<<<(CDIM * HID    + 255) / 256, 256>>>(fc1_w,  wt_fc1,  CDIM, HID);
    transpose_kernel<<<(HID  * CDIM   + 255) / 256, 256>>>(fc2_w,  wt_fc2,  HID,  CDIM);
    bias_kernel<<<dim3(NHEAD, 4), 256>>>(rpb_t, biastab);

    // 1. LN1 + shift + window partition (f16 out)
    ln_kernel<<<lnGrid, 256>>>(x, norm1_g, norm1_b, xw, 1);

    // 2. QKV GEMM [100352,192] @ [192,576] -> f16 qkv
    mma_gemm<0><<<dim3(QKVDIM / 64, NROWS / 128), 128>>>(
        xw, wt_qkv, qkv_b, qkvbuf, nullptr, NROWS, QKVDIM, CDIM);

    // 3. Windowed attention -> f16 ao
    attn_kernel<<<32 * NWIN * NHEAD, 256>>>(qkvbuf, biastab, ao);

    // 4. Projection GEMM + fused un-shift/un-window + residual -> fp32 x1
    mma_gemm<3><<<dim3(CDIM / 64, NROWS / 128), 128>>>(
        ao, wt_proj, proj_b, x1, x, NROWS, CDIM, CDIM);

    // 5. LN2 (f16 out)
    ln_kernel<<<lnGrid, 256>>>(x1, norm2_g, norm2_b, xw, 0);

    // 6. FC1 + exact GELU [100352,192] @ [192,768] -> f16 hidden
    mma_gemm<1><<<dim3(HID / 64, NROWS / 128), 128>>>(
        xw, wt_fc1, fc1_b, hbuf, nullptr, NROWS, HID, CDIM);

    // 7. FC2 + residual [100352,768] @ [768,192] -> fp32 d_out
    mma_gemm<2><<<dim3(CDIM / 64, NROWS / 128), 128>>>(
        hbuf, wt_fc2, fc2_b, out, x1, NROWS, CDIM, HID);
}